// round 15
// baseline (speedup 1.0000x reference)
#include <cuda_runtime.h>
#include <cuda_bf16.h>

#define NBINS    2048
#define CAP      6144         // 48KB smem key cache; M (score ties) ~4000
#define MAXC     300
#define TOPN     100
#define MAXN     1000448
#define NW       5            // ceil(300/64)

#define FB       148          // persistent blocks (1 per SM, co-resident)
#define FT       512

// ---- scratch (device globals; zero-init at load; every launch re-zeroes) ----
__device__ unsigned int       g_keys[MAXN];   // ~bits(m); 0xFFFFFFFF invalid
__device__ unsigned int       g_hist[NBINS];
__device__ unsigned int       g_count;
__device__ unsigned int       g_bar0, g_bar1, g_bar2, g_done;
__device__ unsigned long long g_cand[CAP];
__device__ float4             g_box[MAXC];
__device__ float              g_area[MAXC];
__device__ float              g_pr[MAXC][5];
__device__ unsigned long long g_rm[MAXC * NW];

// relative bin: ascending in f = 1-m (descending in score). Ties at m==1 -> bin 0.
__device__ __forceinline__ int hist_bin(float m) {
    float f = 1.0f - m;
    int b = (int)(__float_as_uint(f) >> 19);
    return min(b, NBINS - 1);
}

__device__ __forceinline__ void decode_core(
    float x1, float y1, float x2, float y2,
    float4 d, float W, float H,
    float& bx1, float& by1, float& bx2, float& by2)
{
    float w  = x2 - x1 + 1.0f;
    float h  = y2 - y1 + 1.0f;
    float cx = x1 + 0.5f*(w - 1.0f);
    float cy = y1 + 0.5f*(h - 1.0f);
    float dx = d.x*0.1f, dy = d.y*0.1f, dw = d.z*0.2f, dh = d.w*0.2f;
    float pcx = dx*w + cx;
    float pcy = dy*h + cy;
    float pw  = expf(dw)*w;
    float ph  = expf(dh)*h;
    bx1 = fminf(fmaxf(pcx - 0.5f*(pw - 1.0f), 0.0f), W);
    by1 = fminf(fmaxf(pcy - 0.5f*(ph - 1.0f), 0.0f), H);
    bx2 = fminf(fmaxf(pcx + 0.5f*(pw - 1.0f), 0.0f), W);
    by2 = fminf(fmaxf(pcy + 0.5f*(ph - 1.0f), 0.0f), H);
}

// grid barrier: all FB blocks co-resident (1 per SM) => spin is safe
__device__ __forceinline__ void grid_bar(unsigned int* ctr, int tid) {
    __syncthreads();
    if (tid == 0) {
        __threadfence();
        atomicAdd(ctr, 1u);
        while (atomicAdd(ctr, 0u) < (unsigned)FB) { }
    }
    __syncthreads();
}

// ============ THE kernel: scan + threshold + collect + rank + NMS ============
__global__ void __launch_bounds__(FT) fused_all(
    const float* __restrict__ cls,
    const float* __restrict__ bbox,
    const float* __restrict__ rois,
    const float* __restrict__ iminfo,
    float* __restrict__ out,
    int ngrp4, int ngrp16, int n)
{
    // one 48KB phase-overlaid shared buffer
    __shared__ __align__(16) unsigned char smraw[49152];
    __shared__ int thr_sh;
    __shared__ int nkept;
    __shared__ bool is_last;

    int tid  = threadIdx.x;
    int lane = tid & 31;
    int wrp  = tid >> 5;

    // ---------------- Phase 0: score scan (k1 work) ----------------
    unsigned int* hist = reinterpret_cast<unsigned int*>(smraw);   // 8KB
    for (int j = tid; j < NBINS/4; j += FT)
        reinterpret_cast<uint4*>(smraw)[j] = make_uint4(0,0,0,0);
    __syncthreads();

    float W = iminfo[1] - 1.0f, H = iminfo[0] - 1.0f;

    for (int g = blockIdx.x*FT + tid; g < ngrp4; g += FB*FT) {
        int base = g * 4;
        bool full = (base + 4 <= n);

        float c[20], r[20];
        if (full) {
            const float4* c4 = reinterpret_cast<const float4*>(cls)  + (size_t)g*5;
            const float4* r4 = reinterpret_cast<const float4*>(rois) + (size_t)g*5;
            #pragma unroll
            for (int q = 0; q < 5; q++) {
                float4 t = c4[q];
                c[4*q]=t.x; c[4*q+1]=t.y; c[4*q+2]=t.z; c[4*q+3]=t.w;
            }
            #pragma unroll
            for (int q = 0; q < 5; q++) {
                float4 t = r4[q];
                r[4*q]=t.x; r[4*q+1]=t.y; r[4*q+2]=t.z; r[4*q+3]=t.w;
            }
        } else {
            #pragma unroll
            for (int q = 0; q < 4; q++) {
                if (base + q < n) {
                    #pragma unroll
                    for (int e = 0; e < 5; e++) {
                        c[q*5+e] = cls [(size_t)(base+q)*5 + e];
                        r[q*5+e] = rois[(size_t)(base+q)*5 + e];
                    }
                }
            }
        }

        unsigned int outk[4];
        #pragma unroll
        for (int q = 0; q < 4; q++) {
            unsigned int key = 0xFFFFFFFFu;
            if (base + q < n) {
                float s0=c[q*5], s1=c[q*5+1], s2=c[q*5+2], s3=c[q*5+3], s4=c[q*5+4];
                float m = s1; int a = 1;
                if (s2 > m) { m = s2; a = 2; }
                if (s3 > m) { m = s3; a = 3; }
                if (s4 > m) { m = s4; a = 4; }
                if ((1.0f - s0 >= 0.2f) && (m > 0.1f)) {
                    float4 d = *reinterpret_cast<const float4*>(
                        bbox + (size_t)(base+q)*20 + a*4);
                    float bx1, by1, bx2, by2;
                    decode_core(r[q*5+1], r[q*5+2], r[q*5+3], r[q*5+4],
                                d, W, H, bx1, by1, bx2, by2);
                    float bw = bx2 - bx1 + 1.0f;
                    float bh = by2 - by1 + 1.0f;
                    if (bw >= 6.0f || bh >= 6.0f) {
                        key = ~__float_as_uint(m);
                        atomicAdd(&hist[hist_bin(m)], 1u);
                    }
                }
            }
            outk[q] = key;
        }

        if (full) {
            *reinterpret_cast<uint4*>(g_keys + base) =
                make_uint4(outk[0], outk[1], outk[2], outk[3]);
        } else {
            #pragma unroll
            for (int q = 0; q < 4; q++)
                if (base + q < n) g_keys[base + q] = outk[q];
        }
    }
    __syncthreads();

    for (int j = tid; j < NBINS; j += FT) {
        unsigned int v = hist[j];
        if (v) atomicAdd(&g_hist[j], v);
    }
    grid_bar(&g_bar0, tid);

    // --------- threshold: computed redundantly per block (L2-hot) ---------
    unsigned int* part = reinterpret_cast<unsigned int*>(smraw + 8192); // 2KB
    {
        unsigned int s = 0;
        #pragma unroll
        for (int j = 0; j < NBINS/FT; j++) s += g_hist[tid*(NBINS/FT) + j];
        part[tid] = s;
    }
    __syncthreads();
    if (tid == 0) {
        unsigned int cum = 0;
        int thr = NBINS - 1;
        for (int cch = 0; cch < FT; cch++) {
            if (cum + part[cch] >= (unsigned)MAXC) {
                int lo = cch * (NBINS/FT);
                for (int b = lo; b < lo + (NBINS/FT); b++) {
                    cum += g_hist[b];
                    if (cum >= (unsigned)MAXC) { thr = b; break; }
                }
                break;
            }
            cum += part[cch];
        }
        thr_sh = thr;
    }
    __syncthreads();
    int thr = thr_sh;

    // ---------------- Phase A: collect candidates ----------------
    for (int g = blockIdx.x*FT + tid; g < ngrp16; g += FB*FT) {
        int base = g * 16;
        uint4 v[4];
        #pragma unroll
        for (int p = 0; p < 4; p++)
            v[p] = reinterpret_cast<const uint4*>(g_keys)[g*4 + p];
        #pragma unroll
        for (int p = 0; p < 4; p++) {
            unsigned int kk[4] = {v[p].x, v[p].y, v[p].z, v[p].w};
            #pragma unroll
            for (int l = 0; l < 4; l++) {
                unsigned int key = kk[l];
                int i = base + p*4 + l;
                if (key != 0xFFFFFFFFu && i < n) {
                    float m = __uint_as_float(~key);
                    if (hist_bin(m) <= thr) {
                        unsigned int pos = atomicAdd(&g_count, 1u);
                        if (pos < CAP)
                            g_cand[pos] = (((unsigned long long)key) << 32) |
                                          (unsigned int)i;
                    }
                }
            }
        }
    }
    grid_bar(&g_bar1, tid);

    // ---------------- Phase B: rank + decode ----------------
    unsigned long long* skeys = reinterpret_cast<unsigned long long*>(smraw);
    int M = (int)min(g_count, (unsigned int)CAP);
    int K = min(M, MAXC);
    for (int t = tid; t < M; t += FT) skeys[t] = g_cand[t];
    __syncthreads();

    int chunk = (M + FB - 1) / FB;
    int kbase = blockIdx.x * chunk;
    int kend  = min(kbase + chunk, M);
    for (int kk = kbase + wrp; kk < kend; kk += FT/32) {
        unsigned long long key = skeys[kk];
        int r = 0;
        for (int j = lane; j < M; j += 32) r += (skeys[j] < key);
        r = __reduce_add_sync(0xFFFFFFFFu, r);
        if (r < MAXC && lane == 0) {
            int i = (int)(unsigned int)(key & 0xFFFFFFFFULL);
            const float* c = cls + (size_t)i*5;
            float c0=c[0], c1=c[1], c2=c[2], c3=c[3], c4=c[4];
            g_pr[r][0]=c0; g_pr[r][1]=c1; g_pr[r][2]=c2;
            g_pr[r][3]=c3; g_pr[r][4]=c4;
            float m = c1; int a = 1;
            if (c2 > m) { m = c2; a = 2; }
            if (c3 > m) { m = c3; a = 3; }
            if (c4 > m) { m = c4; a = 4; }
            float4 d = *reinterpret_cast<const float4*>(bbox + (size_t)i*20 + a*4);
            float bx1, by1, bx2, by2;
            decode_core(rois[(size_t)i*5+1], rois[(size_t)i*5+2],
                        rois[(size_t)i*5+3], rois[(size_t)i*5+4],
                        d, W, H, bx1, by1, bx2, by2);
            g_box[r]  = make_float4(bx1, by1, bx2, by2);
            g_area[r] = (bx2 - bx1) * (by2 - by1);
        }
    }
    grid_bar(&g_bar2, tid);

    // ---------------- Phase C: bitmatrix strips ----------------
    float4* bx4 = reinterpret_cast<float4*>(smraw);                 // 4800B
    float*  area = reinterpret_cast<float*>(smraw + 4800);          // 1200B
    unsigned long long* srm =
        reinterpret_cast<unsigned long long*>(smraw + 6144);        // 12000B
    int* kept = reinterpret_cast<int*>(smraw + 6144 + 12000);       // 400B

    for (int t = tid; t < K; t += FT) {
        bx4[t]  = g_box[t];
        area[t] = g_area[t];
    }
    __syncthreads();

    for (int task = blockIdx.x*FT + tid; task < K*NW; task += FB*FT) {
        int i = task / NW;
        int w = task % NW;
        float4 a4 = bx4[i];
        float aa = area[i];
        unsigned long long bits = 0ULL;
        int j0 = max(i + 1, w*64);
        int j1 = min(K, w*64 + 64);
        for (int j = j0; j < j1; j++) {
            float4 b4 = bx4[j];
            float lx = fmaxf(a4.x, b4.x);
            float ly = fmaxf(a4.y, b4.y);
            float rx = fminf(a4.z, b4.z);
            float ry = fminf(a4.w, b4.w);
            float iw = fmaxf(rx - lx, 0.0f);
            float ih = fmaxf(ry - ly, 0.0f);
            float inter = iw * ih;
            float iou = inter / (aa + area[j] - inter);
            if (iou > 0.5f) bits |= 1ULL << (j - w*64);
        }
        g_rm[task] = bits;
    }

    // ---------------- last block: walk + output + reset ----------------
    __threadfence();
    __syncthreads();
    if (tid == 0)
        is_last = (atomicAdd(&g_done, 1u) == FB - 1);
    __syncthreads();
    if (!is_last) return;

    for (int t = tid; t < K*NW; t += FT) srm[t] = g_rm[t];
    __syncthreads();

    if (tid == 0) {
        unsigned long long sup1=0, sup2=0, sup3=0, sup4=0;
        int cnt = 0;

        #define WALK_WORD(WD, SUPIN, ORS)                                     \
        if (cnt < TOPN && K > (WD)*64) {                                      \
            int nb = K - (WD)*64; if (nb > 64) nb = 64;                       \
            unsigned long long alive =                                        \
                ((nb >= 64) ? ~0ULL : ((1ULL << nb) - 1ULL)) & ~(SUPIN);      \
            while (alive && cnt < TOPN) {                                     \
                int b = __ffsll((long long)alive) - 1;                        \
                int i = (WD)*64 + b;                                          \
                kept[cnt++] = i;                                              \
                alive &= ~srm[i*NW + (WD)];                                   \
                alive &= ~(1ULL << b);                                        \
                ORS                                                           \
            }                                                                 \
        }

        WALK_WORD(0, 0ULL,
            { sup1 |= srm[i*NW+1]; sup2 |= srm[i*NW+2];
              sup3 |= srm[i*NW+3]; sup4 |= srm[i*NW+4]; })
        WALK_WORD(1, sup1,
            { sup2 |= srm[i*NW+2]; sup3 |= srm[i*NW+3]; sup4 |= srm[i*NW+4]; })
        WALK_WORD(2, sup2,
            { sup3 |= srm[i*NW+3]; sup4 |= srm[i*NW+4]; })
        WALK_WORD(3, sup3,
            { sup4 |= srm[i*NW+4]; })
        WALK_WORD(4, sup4, { })
        #undef WALK_WORD

        nkept = cnt;
    }
    __syncthreads();

    for (int t = tid; t < TOPN*10; t += FT) out[t] = 0.0f;
    __syncthreads();
    int nk = nkept;
    for (int r = tid; r < nk; r += FT) {
        int i = kept[r];
        float4 b = bx4[i];
        float* o = out + r*10;
        o[0] = 0.0f;
        o[1] = b.x; o[2] = b.y; o[3] = b.z; o[4] = b.w;
        o[5] = g_pr[i][0]; o[6] = g_pr[i][1]; o[7] = g_pr[i][2];
        o[8] = g_pr[i][3]; o[9] = g_pr[i][4];
    }

    // reset ALL device state for the next graph replay
    for (int j = tid; j < NBINS/4; j += FT)
        reinterpret_cast<uint4*>(g_hist)[j] = make_uint4(0,0,0,0);
    if (tid == 0) {
        g_count = 0u; g_bar0 = 0u; g_bar1 = 0u; g_bar2 = 0u; g_done = 0u;
    }
}

// ---------------- launch ----------------
extern "C" void kernel_launch(void* const* d_in, const int* in_sizes, int n_in,
                              void* d_out, int out_size)
{
    const float* cls    = (const float*)d_in[0];
    const float* bbox   = (const float*)d_in[1];
    const float* rois   = (const float*)d_in[2];
    const float* iminfo = (const float*)d_in[3];
    float* out = (float*)d_out;
    int n = in_sizes[0] / 5;
    if (n > MAXN) n = MAXN;

    int ngrp4  = (n + 3) / 4;
    int ngrp16 = (n + 15) / 16;

    fused_all<<<FB, FT>>>(cls, bbox, rois, iminfo, out, ngrp4, ngrp16, n);
}

// round 16
// speedup vs baseline: 1.0760x; 1.0760x over previous
#include <cuda_runtime.h>
#include <cuda_bf16.h>

#define NBINS    2048
#define CAP      6144         // 48KB smem key cache; M (score ties) ~4000
#define MAXC     300
#define TOPN     100
#define MAXN     1000448
#define NW       5            // ceil(300/64)

#define FB       296          // persistent blocks (2 per SM, co-resident)
#define FT       512

// ---- scratch (device globals; zero-init at load; every launch re-zeroes) ----
__device__ unsigned int       g_keys[MAXN];   // ~bits(m); 0xFFFFFFFF invalid
__device__ unsigned int       g_hist[NBINS];
__device__ unsigned int       g_count;
__device__ unsigned int       g_bar0, g_bar1, g_bar2, g_done;
__device__ unsigned long long g_cand[CAP];
__device__ float4             g_box[MAXC];
__device__ float              g_area[MAXC];
__device__ float              g_pr[MAXC][5];
__device__ unsigned long long g_rm[MAXC * NW];

// relative bin: ascending in f = 1-m (descending in score). Ties at m==1 -> bin 0.
__device__ __forceinline__ int hist_bin(float m) {
    float f = 1.0f - m;
    int b = (int)(__float_as_uint(f) >> 19);
    return min(b, NBINS - 1);
}

__device__ __forceinline__ void decode_core(
    float x1, float y1, float x2, float y2,
    float4 d, float W, float H,
    float& bx1, float& by1, float& bx2, float& by2)
{
    float w  = x2 - x1 + 1.0f;
    float h  = y2 - y1 + 1.0f;
    float cx = x1 + 0.5f*(w - 1.0f);
    float cy = y1 + 0.5f*(h - 1.0f);
    float dx = d.x*0.1f, dy = d.y*0.1f, dw = d.z*0.2f, dh = d.w*0.2f;
    float pcx = dx*w + cx;
    float pcy = dy*h + cy;
    float pw  = expf(dw)*w;
    float ph  = expf(dh)*h;
    bx1 = fminf(fmaxf(pcx - 0.5f*(pw - 1.0f), 0.0f), W);
    by1 = fminf(fmaxf(pcy - 0.5f*(ph - 1.0f), 0.0f), H);
    bx2 = fminf(fmaxf(pcx + 0.5f*(pw - 1.0f), 0.0f), W);
    by2 = fminf(fmaxf(pcy + 0.5f*(ph - 1.0f), 0.0f), H);
}

// grid barrier: all FB blocks co-resident (2 per SM, guaranteed by
// __launch_bounds__(FT,2): regs<=64, smem 49KB*2<228KB) => spin is safe
__device__ __forceinline__ void grid_bar(unsigned int* ctr, int tid) {
    __syncthreads();
    if (tid == 0) {
        __threadfence();
        atomicAdd(ctr, 1u);
        while (atomicAdd(ctr, 0u) < (unsigned)FB) { }
    }
    __syncthreads();
}

// ============ THE kernel: scan + threshold + collect + rank + NMS ============
__global__ void __launch_bounds__(FT, 2) fused_all(
    const float* __restrict__ cls,
    const float* __restrict__ bbox,
    const float* __restrict__ rois,
    const float* __restrict__ iminfo,
    float* __restrict__ out,
    int ngrp4, int ngrp16, int n)
{
    // one 48KB phase-overlaid shared buffer
    __shared__ __align__(16) unsigned char smraw[49152];
    __shared__ int thr_sh;
    __shared__ int nkept;
    __shared__ bool is_last;

    int tid  = threadIdx.x;
    int lane = tid & 31;
    int wrp  = tid >> 5;

    // ---------------- Phase 0: score scan ----------------
    unsigned int* hist = reinterpret_cast<unsigned int*>(smraw);   // 8KB
    for (int j = tid; j < NBINS/4; j += FT)
        reinterpret_cast<uint4*>(smraw)[j] = make_uint4(0,0,0,0);
    __syncthreads();

    float W = iminfo[1] - 1.0f, H = iminfo[0] - 1.0f;

    for (int g = blockIdx.x*FT + tid; g < ngrp4; g += FB*FT) {
        int base = g * 4;
        bool full = (base + 4 <= n);

        float c[20], r[20];
        if (full) {
            const float4* c4 = reinterpret_cast<const float4*>(cls)  + (size_t)g*5;
            const float4* r4 = reinterpret_cast<const float4*>(rois) + (size_t)g*5;
            #pragma unroll
            for (int q = 0; q < 5; q++) {
                float4 t = c4[q];
                c[4*q]=t.x; c[4*q+1]=t.y; c[4*q+2]=t.z; c[4*q+3]=t.w;
            }
            #pragma unroll
            for (int q = 0; q < 5; q++) {
                float4 t = r4[q];
                r[4*q]=t.x; r[4*q+1]=t.y; r[4*q+2]=t.z; r[4*q+3]=t.w;
            }
        } else {
            #pragma unroll
            for (int q = 0; q < 4; q++) {
                if (base + q < n) {
                    #pragma unroll
                    for (int e = 0; e < 5; e++) {
                        c[q*5+e] = cls [(size_t)(base+q)*5 + e];
                        r[q*5+e] = rois[(size_t)(base+q)*5 + e];
                    }
                }
            }
        }

        unsigned int outk[4];
        #pragma unroll
        for (int q = 0; q < 4; q++) {
            unsigned int key = 0xFFFFFFFFu;
            if (base + q < n) {
                float s0=c[q*5], s1=c[q*5+1], s2=c[q*5+2], s3=c[q*5+3], s4=c[q*5+4];
                float m = s1; int a = 1;
                if (s2 > m) { m = s2; a = 2; }
                if (s3 > m) { m = s3; a = 3; }
                if (s4 > m) { m = s4; a = 4; }
                if ((1.0f - s0 >= 0.2f) && (m > 0.1f)) {
                    float4 d = *reinterpret_cast<const float4*>(
                        bbox + (size_t)(base+q)*20 + a*4);
                    float bx1, by1, bx2, by2;
                    decode_core(r[q*5+1], r[q*5+2], r[q*5+3], r[q*5+4],
                                d, W, H, bx1, by1, bx2, by2);
                    float bw = bx2 - bx1 + 1.0f;
                    float bh = by2 - by1 + 1.0f;
                    if (bw >= 6.0f || bh >= 6.0f) {
                        key = ~__float_as_uint(m);
                        atomicAdd(&hist[hist_bin(m)], 1u);
                    }
                }
            }
            outk[q] = key;
        }

        if (full) {
            *reinterpret_cast<uint4*>(g_keys + base) =
                make_uint4(outk[0], outk[1], outk[2], outk[3]);
        } else {
            #pragma unroll
            for (int q = 0; q < 4; q++)
                if (base + q < n) g_keys[base + q] = outk[q];
        }
    }
    __syncthreads();

    for (int j = tid; j < NBINS; j += FT) {
        unsigned int v = hist[j];
        if (v) atomicAdd(&g_hist[j], v);
    }
    grid_bar(&g_bar0, tid);

    // --------- threshold: computed redundantly per block (L2-hot) ---------
    unsigned int* part = reinterpret_cast<unsigned int*>(smraw + 8192); // 2KB
    {
        unsigned int s = 0;
        #pragma unroll
        for (int j = 0; j < NBINS/FT; j++) s += g_hist[tid*(NBINS/FT) + j];
        part[tid] = s;
    }
    __syncthreads();
    if (tid == 0) {
        unsigned int cum = 0;
        int thr = NBINS - 1;
        for (int cch = 0; cch < FT; cch++) {
            if (cum + part[cch] >= (unsigned)MAXC) {
                int lo = cch * (NBINS/FT);
                for (int b = lo; b < lo + (NBINS/FT); b++) {
                    cum += g_hist[b];
                    if (cum >= (unsigned)MAXC) { thr = b; break; }
                }
                break;
            }
            cum += part[cch];
        }
        thr_sh = thr;
    }
    __syncthreads();
    int thr = thr_sh;

    // ---------------- Phase A: collect candidates ----------------
    for (int g = blockIdx.x*FT + tid; g < ngrp16; g += FB*FT) {
        int base = g * 16;
        uint4 v[4];
        #pragma unroll
        for (int p = 0; p < 4; p++)
            v[p] = reinterpret_cast<const uint4*>(g_keys)[g*4 + p];
        #pragma unroll
        for (int p = 0; p < 4; p++) {
            unsigned int kk[4] = {v[p].x, v[p].y, v[p].z, v[p].w};
            #pragma unroll
            for (int l = 0; l < 4; l++) {
                unsigned int key = kk[l];
                int i = base + p*4 + l;
                if (key != 0xFFFFFFFFu && i < n) {
                    float m = __uint_as_float(~key);
                    if (hist_bin(m) <= thr) {
                        unsigned int pos = atomicAdd(&g_count, 1u);
                        if (pos < CAP)
                            g_cand[pos] = (((unsigned long long)key) << 32) |
                                          (unsigned int)i;
                    }
                }
            }
        }
    }
    grid_bar(&g_bar1, tid);

    // ---------------- Phase B: rank + decode ----------------
    unsigned long long* skeys = reinterpret_cast<unsigned long long*>(smraw);
    int M = (int)min(g_count, (unsigned int)CAP);
    int K = min(M, MAXC);
    for (int t = tid; t < M; t += FT) skeys[t] = g_cand[t];
    __syncthreads();

    int chunk = (M + FB - 1) / FB;
    int kbase = blockIdx.x * chunk;
    int kend  = min(kbase + chunk, M);
    for (int kk = kbase + wrp; kk < kend; kk += FT/32) {
        unsigned long long key = skeys[kk];
        int r = 0;
        for (int j = lane; j < M; j += 32) r += (skeys[j] < key);
        r = __reduce_add_sync(0xFFFFFFFFu, r);
        if (r < MAXC && lane == 0) {
            int i = (int)(unsigned int)(key & 0xFFFFFFFFULL);
            const float* c = cls + (size_t)i*5;
            float c0=c[0], c1=c[1], c2=c[2], c3=c[3], c4=c[4];
            g_pr[r][0]=c0; g_pr[r][1]=c1; g_pr[r][2]=c2;
            g_pr[r][3]=c3; g_pr[r][4]=c4;
            float m = c1; int a = 1;
            if (c2 > m) { m = c2; a = 2; }
            if (c3 > m) { m = c3; a = 3; }
            if (c4 > m) { m = c4; a = 4; }
            float4 d = *reinterpret_cast<const float4*>(bbox + (size_t)i*20 + a*4);
            float bx1, by1, bx2, by2;
            decode_core(rois[(size_t)i*5+1], rois[(size_t)i*5+2],
                        rois[(size_t)i*5+3], rois[(size_t)i*5+4],
                        d, W, H, bx1, by1, bx2, by2);
            g_box[r]  = make_float4(bx1, by1, bx2, by2);
            g_area[r] = (bx2 - bx1) * (by2 - by1);
        }
    }
    grid_bar(&g_bar2, tid);

    // ---------------- Phase C: bitmatrix strips ----------------
    float4* bx4 = reinterpret_cast<float4*>(smraw);                 // 4800B
    float*  area = reinterpret_cast<float*>(smraw + 4800);          // 1200B
    unsigned long long* srm =
        reinterpret_cast<unsigned long long*>(smraw + 6144);        // 12000B
    int* kept = reinterpret_cast<int*>(smraw + 6144 + 12000);       // 400B

    for (int t = tid; t < K; t += FT) {
        bx4[t]  = g_box[t];
        area[t] = g_area[t];
    }
    __syncthreads();

    for (int task = blockIdx.x*FT + tid; task < K*NW; task += FB*FT) {
        int i = task / NW;
        int w = task % NW;
        float4 a4 = bx4[i];
        float aa = area[i];
        unsigned long long bits = 0ULL;
        int j0 = max(i + 1, w*64);
        int j1 = min(K, w*64 + 64);
        for (int j = j0; j < j1; j++) {
            float4 b4 = bx4[j];
            float lx = fmaxf(a4.x, b4.x);
            float ly = fmaxf(a4.y, b4.y);
            float rx = fminf(a4.z, b4.z);
            float ry = fminf(a4.w, b4.w);
            float iw = fmaxf(rx - lx, 0.0f);
            float ih = fmaxf(ry - ly, 0.0f);
            float inter = iw * ih;
            float iou = inter / (aa + area[j] - inter);
            if (iou > 0.5f) bits |= 1ULL << (j - w*64);
        }
        g_rm[task] = bits;
    }

    // ---------------- last block: walk + output + reset ----------------
    __threadfence();
    __syncthreads();
    if (tid == 0)
        is_last = (atomicAdd(&g_done, 1u) == FB - 1);
    __syncthreads();
    if (!is_last) return;

    for (int t = tid; t < K*NW; t += FT) srm[t] = g_rm[t];
    __syncthreads();

    if (tid == 0) {
        unsigned long long sup1=0, sup2=0, sup3=0, sup4=0;
        int cnt = 0;

        #define WALK_WORD(WD, SUPIN, ORS)                                     \
        if (cnt < TOPN && K > (WD)*64) {                                      \
            int nb = K - (WD)*64; if (nb > 64) nb = 64;                       \
            unsigned long long alive =                                        \
                ((nb >= 64) ? ~0ULL : ((1ULL << nb) - 1ULL)) & ~(SUPIN);      \
            while (alive && cnt < TOPN) {                                     \
                int b = __ffsll((long long)alive) - 1;                        \
                int i = (WD)*64 + b;                                          \
                kept[cnt++] = i;                                              \
                alive &= ~srm[i*NW + (WD)];                                   \
                alive &= ~(1ULL << b);                                        \
                ORS                                                           \
            }                                                                 \
        }

        WALK_WORD(0, 0ULL,
            { sup1 |= srm[i*NW+1]; sup2 |= srm[i*NW+2];
              sup3 |= srm[i*NW+3]; sup4 |= srm[i*NW+4]; })
        WALK_WORD(1, sup1,
            { sup2 |= srm[i*NW+2]; sup3 |= srm[i*NW+3]; sup4 |= srm[i*NW+4]; })
        WALK_WORD(2, sup2,
            { sup3 |= srm[i*NW+3]; sup4 |= srm[i*NW+4]; })
        WALK_WORD(3, sup3,
            { sup4 |= srm[i*NW+4]; })
        WALK_WORD(4, sup4, { })
        #undef WALK_WORD

        nkept = cnt;
    }
    __syncthreads();

    for (int t = tid; t < TOPN*10; t += FT) out[t] = 0.0f;
    __syncthreads();
    int nk = nkept;
    for (int r = tid; r < nk; r += FT) {
        int i = kept[r];
        float4 b = bx4[i];
        float* o = out + r*10;
        o[0] = 0.0f;
        o[1] = b.x; o[2] = b.y; o[3] = b.z; o[4] = b.w;
        o[5] = g_pr[i][0]; o[6] = g_pr[i][1]; o[7] = g_pr[i][2];
        o[8] = g_pr[i][3]; o[9] = g_pr[i][4];
    }

    // reset ALL device state for the next graph replay
    for (int j = tid; j < NBINS/4; j += FT)
        reinterpret_cast<uint4*>(g_hist)[j] = make_uint4(0,0,0,0);
    if (tid == 0) {
        g_count = 0u; g_bar0 = 0u; g_bar1 = 0u; g_bar2 = 0u; g_done = 0u;
    }
}

// ---------------- launch ----------------
extern "C" void kernel_launch(void* const* d_in, const int* in_sizes, int n_in,
                              void* d_out, int out_size)
{
    const float* cls    = (const float*)d_in[0];
    const float* bbox   = (const float*)d_in[1];
    const float* rois   = (const float*)d_in[2];
    const float* iminfo = (const float*)d_in[3];
    float* out = (float*)d_out;
    int n = in_sizes[0] / 5;
    if (n > MAXN) n = MAXN;

    int ngrp4  = (n + 3) / 4;
    int ngrp16 = (n + 15) / 16;

    fused_all<<<FB, FT>>>(cls, bbox, rois, iminfo, out, ngrp4, ngrp16, n);
}